// round 6
// baseline (speedup 1.0000x reference)
#include <cuda_runtime.h>

#define EPSBN 1e-5f
#define ALPHA 0.2f

typedef unsigned long long ull;

static constexpr int B = 16, N = 4096, P = 1024, S = 32;
static constexpr int NTILES = (B * P) / 4;   // 4096 tiles, 4 groups each
static constexpr int OUT2_OFF = B * 3 * P;   // 49152
static constexpr int THREADS = 512;

// fused transposed features: [b][n][0..2]=xyz, [3..66]=points, [67]=0
__device__ __align__(16) float g_xpt[(size_t)B * N * 68];
// BN-folded weights+biases, laid out exactly like the smem WBUF block
__device__ __align__(16) float g_wfold[17664];
// a transposed to k-major: g_aT[d*132 + k] = a[3+k][d] (k<128),
// cols 128..130 = a[0..2][d] (xyz part), col 131 = 0
__device__ __align__(16) float g_aT[128 * 132];

// ---------------------------------------------------------------------------
// packed f32x2 helpers
// ---------------------------------------------------------------------------
__device__ __forceinline__ void ffma2(ull& d, ull a, ull b) {
    asm("fma.rn.f32x2 %0, %1, %2, %0;" : "+l"(d) : "l"(a), "l"(b));
}
__device__ __forceinline__ float hsum2(ull v) {
    float lo, hi;
    asm("mov.b64 {%0, %1}, %2;" : "=f"(lo), "=f"(hi) : "l"(v));
    return lo + hi;
}

// ---------------------------------------------------------------------------
// Kernel 1: transpose (B,3,N)+(B,64,N) channel-major -> (B,N,68) row-major
// ---------------------------------------------------------------------------
__global__ void __launch_bounds__(256) transpose_kernel(
    const float* __restrict__ xyz, const float* __restrict__ pts)
{
    __shared__ float sm[67 * 65];
    int b  = blockIdx.x >> 6;
    int n0 = (blockIdx.x & 63) << 6;
    int t  = threadIdx.x;
    for (int idx = t; idx < 67 * 64; idx += 256) {
        int c = idx >> 6, i = idx & 63;
        float v = (c < 3) ? xyz[(b * 3 + c) * N + n0 + i]
                          : pts[(b * 64 + (c - 3)) * N + n0 + i];
        sm[c * 65 + i] = v;
    }
    __syncthreads();
    for (int idx = t; idx < 64 * 17; idx += 256) {
        int row = idx / 17, c4 = idx % 17;
        int cb = c4 << 2;
        float4 v;
        v.x = sm[(cb + 0) * 65 + row];
        v.y = sm[(cb + 1) * 65 + row];
        v.z = sm[(cb + 2) * 65 + row];
        v.w = (cb + 3 < 67) ? sm[(cb + 3) * 65 + row] : 0.f;
        *(float4*)&g_xpt[((size_t)(b * N + n0 + row)) * 68 + cb] = v;
    }
}

// ---------------------------------------------------------------------------
// Kernel 2: fold BN into weights once; transpose 'a' to k-major
// ---------------------------------------------------------------------------
__global__ void __launch_bounds__(256) prep_kernel(
    const float* __restrict__ w1, const float* __restrict__ b1,
    const float* __restrict__ g1, const float* __restrict__ bt1,
    const float* __restrict__ m1, const float* __restrict__ v1,
    const float* __restrict__ w2, const float* __restrict__ b2,
    const float* __restrict__ g2, const float* __restrict__ bt2,
    const float* __restrict__ m2, const float* __restrict__ v2,
    const float* __restrict__ w3, const float* __restrict__ b3,
    const float* __restrict__ g3, const float* __restrict__ bt3,
    const float* __restrict__ m3, const float* __restrict__ v3,
    const float* __restrict__ aG)
{
    int i = blockIdx.x * 256 + threadIdx.x;
    if (i < 17664) {
        float val;
        if (i < 4352) {
            int d = i / 68, k = i % 68;
            float s = g1[d] * rsqrtf(v1[d] + EPSBN);
            val = (k < 67) ? w1[d * 67 + k] * s : 0.f;
        } else if (i < 8704) {
            int j = i - 4352, d = j / 68, k = j % 68;
            float s = g2[d] * rsqrtf(v2[d] + EPSBN);
            val = (k < 64) ? w2[d * 64 + k] * s : 0.f;
        } else if (i < 17408) {
            int j = i - 8704, d = j / 68, k = j % 68;
            float s = g3[d] * rsqrtf(v3[d] + EPSBN);
            val = (k < 64) ? w3[d * 64 + k] * s : 0.f;
        } else if (i < 17472) {
            int d = i - 17408;
            float s = g1[d] * rsqrtf(v1[d] + EPSBN);
            val = (b1[d] - m1[d]) * s + bt1[d];
        } else if (i < 17536) {
            int d = i - 17472;
            float s = g2[d] * rsqrtf(v2[d] + EPSBN);
            val = (b2[d] - m2[d]) * s + bt2[d];
        } else {
            int d = i - 17536;
            float s = g3[d] * rsqrtf(v3[d] + EPSBN);
            val = (b3[d] - m3[d]) * s + bt3[d];
        }
        g_wfold[i] = val;
    } else if (i < 17664 + 128 * 132) {
        int j = i - 17664;
        int d = j / 132, k = j % 132;
        float val;
        if (k < 128)       val = aG[(3 + k) * 128 + d];
        else if (k < 131)  val = aG[(k - 128) * 128 + d];
        else               val = 0.f;
        g_aT[j] = val;
    }
}

// ---------------------------------------------------------------------------
// Shared-memory GEMM (f32x2 packed over K), 512 threads:
// out[r][d] = act(sum_k in[r][k]*W[d][k] (+ bias[d]))
// Thread tiling: 2 rows x 8 cols (d strided by 8 -> bank-clean for
// stride 68 and 132, both = 4 banks per row step).
// rb = t>>3 covers rows 0..127; rb 64,65 (threads 0..15) cover rows 128..131.
// ---------------------------------------------------------------------------
template<bool RELU>
__device__ __forceinline__ void gemm_core(
    const float* __restrict__ sIn, int inStride,
    const float* __restrict__ sW, int wStride,
    const float* __restrict__ sBias, float* __restrict__ sOut,
    int outStride, int K4, int dOff, int t)
{
    int d_blk = t & 7;
    int rb0   = t >> 3;
    for (int rb = rb0; rb < 66; rb += 64) {
        int r0 = rb << 1;
        ull acc[2][8];
#pragma unroll
        for (int i = 0; i < 2; i++)
#pragma unroll
            for (int j = 0; j < 8; j++) acc[i][j] = 0ull;
        for (int k4 = 0; k4 < K4; k4++) {
            ulonglong2 xv[2];
#pragma unroll
            for (int i = 0; i < 2; i++)
                xv[i] = *(const ulonglong2*)&sIn[(r0 + i) * inStride + (k4 << 2)];
#pragma unroll
            for (int j = 0; j < 8; j++) {
                ulonglong2 wv = *(const ulonglong2*)&sW[(dOff + d_blk + (j << 3)) * wStride + (k4 << 2)];
#pragma unroll
                for (int i = 0; i < 2; i++) {
                    ffma2(acc[i][j], xv[i].x, wv.x);
                    ffma2(acc[i][j], xv[i].y, wv.y);
                }
            }
        }
#pragma unroll
        for (int j = 0; j < 8; j++) {
            int d = dOff + d_blk + (j << 3);
            float bb = RELU ? sBias[d] : 0.f;
#pragma unroll
            for (int i = 0; i < 2; i++) {
                float v = hsum2(acc[i][j]) + bb;
                if (RELU) v = v > 0.f ? v : 0.f;
                sOut[(r0 + i) * outStride + d] = v;
            }
        }
    }
}

// ---------------------------------------------------------------------------
// Main fused kernel: persistent CTAs, each tile = 4 groups (132 rows)
// smem layout (floats):
//  WBUF 0(17664): W1s@0 W2s@4352 W3s@8704 c1@17408 c2@17472 c3@17536
//  X 17664(8976)  H1 26640(8976)  H3 35616(17424)
//  relx 53040(384) nX 53424(16) rowGi 53440(132) -> 53572 floats
// During attention: aT (128x132) overlays X+H1; E (132x132) overlays WBUF.
// ---------------------------------------------------------------------------
__global__ void __launch_bounds__(THREADS, 1) main_kernel(
    const int* __restrict__ fpsIdx, const int* __restrict__ grpIdx,
    float* __restrict__ out)
{
    extern __shared__ float sm[];
    float* WBUF = sm;                  // also E during attention (stride 132)
    float* c1s  = sm + 17408;
    float* c2s  = sm + 17472;
    float* c3s  = sm + 17536;
    float* X    = sm + 17664;          // also aT during attention
    float* H1   = sm + 26640;
    float* H3   = sm + 35616;
    float* relx = sm + 53040;
    float* nX   = sm + 53424;
    int*  rowGi = (int*)(sm + 53440);
    float* aSm  = X;                   // 128 x 132, k-major
    float* E    = sm;                  // 132 x 132

    int t = threadIdx.x;

    for (int tile = blockIdx.x; tile < NTILES; tile += gridDim.x) {
        __syncthreads();                       // protect smem from prev tile
        int b  = tile >> 8;
        int p0 = (tile & 255) << 2;

        // reload folded weights (WBUF clobbered by E last tile)
        for (int idx = t; idx < 17664 / 4; idx += THREADS)
            *(float4*)&WBUF[idx << 2] = *(const float4*)&g_wfold[idx << 2];

        if (t < 132) {
            int gi;
            if (t < 128) gi = grpIdx[((b * P + p0 + (t >> 5)) << 5) + (t & 31)];
            else         gi = fpsIdx[b * P + p0 + (t - 128)];
            rowGi[t] = gi;
        }
        __syncthreads();
        if (t < 12) {
            int p = t / 3, c = t % 3;
            float v = g_xpt[((size_t)(b * N + rowGi[128 + p])) * 68 + c];
            nX[p * 4 + c] = v;
            out[(b * 3 + c) * P + p0 + p] = v;   // new_xyz output (B,3,P)
        }
        __syncthreads();

        // gather 132 feature rows (67 valid floats each)
        for (int idx = t; idx < 132 * 17; idx += THREADS) {
            int row = idx / 17, c4 = idx % 17;
            float4 v = *(const float4*)&g_xpt[((size_t)(b * N + rowGi[row])) * 68 + (c4 << 2)];
            if (c4 == 0 && row < 128) {          // relative xyz for neighbor rows
                int p = row >> 5;
                v.x -= nX[p * 4 + 0];
                v.y -= nX[p * 4 + 1];
                v.z -= nX[p * 4 + 2];
                relx[row * 3 + 0] = v.x;
                relx[row * 3 + 1] = v.y;
                relx[row * 3 + 2] = v.z;
            }
            *(float4*)&X[row * 68 + (c4 << 2)] = v;
        }
        __syncthreads();

        gemm_core<true>(X,  68, WBUF,        68, c1s, H1, 68,  17, 0,  t); // 67->64
        __syncthreads();
        gemm_core<true>(H1, 68, WBUF + 4352, 68, c2s, X,  68,  16, 0,  t); // 64->64
        __syncthreads();
        gemm_core<true>(X,  68, WBUF + 8704, 68, c3s, H3, 132, 16, 0,  t); // 64->128
        gemm_core<true>(X,  68, WBUF + 8704, 68, c3s, H3, 132, 16, 64, t);
        __syncthreads();

        // load aT (k-major) into freed X+H1 region
        for (int idx = t; idx < (128 * 132) / 4; idx += THREADS)
            *(float4*)&aSm[idx << 2] = *(const float4*)&g_aT[idx << 2];
        __syncthreads();

        // E[r][d] = H3[r] . a3[d]   (rows 128..131 give fps.a3 = Fp)
        gemm_core<false>(H3, 132, aSm, 132, nullptr, E, 132, 32, 0,  t);
        gemm_core<false>(H3, 132, aSm, 132, nullptr, E, 132, 32, 64, t);
        __syncthreads();

        // softmax + pool: thread owns one (p,d) column (512 = 4*128 columns)
        {
            int w = t >> 5, lane = t & 31;
            int pl = w >> 2;                         // local group 0..3
            int d  = ((w & 3) << 5) + lane;          // channel 0..127
            float Fpd = E[(128 + pl) * 132 + d];
            float av0 = aSm[d * 132 + 128];
            float av1 = aSm[d * 132 + 129];
            float av2 = aSm[d * 132 + 130];
            float nx0 = nX[pl * 4 + 0], nx1 = nX[pl * 4 + 1], nx2 = nX[pl * 4 + 2];
            float ev_arr[32];
            float mx = -1e30f;
#pragma unroll
            for (int r = 0; r < 32; r++) {
                int row = (pl << 5) + r;
                float ev = Fpd - E[row * 132 + d]
                    + (nx0 - relx[row * 3 + 0]) * av0
                    + (nx1 - relx[row * 3 + 1]) * av1
                    + (nx2 - relx[row * 3 + 2]) * av2;
                ev = ev > 0.f ? ev : ALPHA * ev;      // leaky relu
                ev_arr[r] = ev;
                mx = fmaxf(mx, ev);
            }
            float ssum = 0.f;
            float pooled = 0.f;
#pragma unroll
            for (int r = 0; r < 32; r++) {
                float ee = __expf(ev_arr[r] - mx);
                ssum += ee;
                pooled += ee * H3[((pl << 5) + r) * 132 + d];
            }
            out[OUT2_OFF + (b * 128 + d) * P + p0 + pl] = pooled / ssum;
        }
    }
}

// ---------------------------------------------------------------------------
extern "C" void kernel_launch(void* const* d_in, const int* in_sizes, int n_in,
                              void* d_out, int out_size) {
    const float* xyz    = (const float*)d_in[0];
    const float* pts    = (const float*)d_in[1];
    const int*   fpsIdx = (const int*)d_in[2];
    const int*   grpIdx = (const int*)d_in[3];
    const float* w1 = (const float*)d_in[4];
    const float* b1 = (const float*)d_in[5];
    const float* g1 = (const float*)d_in[6];
    const float* bt1 = (const float*)d_in[7];
    const float* m1 = (const float*)d_in[8];
    const float* v1 = (const float*)d_in[9];
    const float* w2 = (const float*)d_in[10];
    const float* b2 = (const float*)d_in[11];
    const float* g2 = (const float*)d_in[12];
    const float* bt2 = (const float*)d_in[13];
    const float* m2 = (const float*)d_in[14];
    const float* v2 = (const float*)d_in[15];
    const float* w3 = (const float*)d_in[16];
    const float* b3 = (const float*)d_in[17];
    const float* g3 = (const float*)d_in[18];
    const float* bt3 = (const float*)d_in[19];
    const float* m3 = (const float*)d_in[20];
    const float* v3 = (const float*)d_in[21];
    const float* aG = (const float*)d_in[22];
    float* out = (float*)d_out;

    transpose_kernel<<<1024, 256>>>(xyz, pts);
    prep_kernel<<<(17664 + 128 * 132 + 255) / 256, 256>>>(
        w1, b1, g1, bt1, m1, v1,
        w2, b2, g2, bt2, m2, v2,
        w3, b3, g3, bt3, m3, v3, aG);

    const int smBytes = 53572 * 4;   // 214288 B
    cudaFuncSetAttribute(main_kernel,
                         cudaFuncAttributeMaxDynamicSharedMemorySize, smBytes);
    int smCount = 148;
    cudaDeviceGetAttribute(&smCount, cudaDevAttrMultiProcessorCount, 0);

    main_kernel<<<smCount, THREADS, smBytes>>>(fpsIdx, grpIdx, out);
}

// round 7
// speedup vs baseline: 1.1650x; 1.1650x over previous
#include <cuda_runtime.h>

#define EPSBN 1e-5f
#define ALPHA 0.2f

typedef unsigned long long ull;

static constexpr int B = 16, N = 4096, P = 1024, S = 32;
static constexpr int NTILES = (B * P) / 4;   // 4096 tiles, 4 groups each
static constexpr int OUT2_OFF = B * 3 * P;   // 49152

// fused transposed features: [b][n][0..2]=xyz, [3..66]=points, [67]=0
__device__ __align__(16) float g_xpt[(size_t)B * N * 68];

// ---------------------------------------------------------------------------
// packed f32x2 helpers
// ---------------------------------------------------------------------------
__device__ __forceinline__ void ffma2(ull& d, ull a, ull b) {
    asm("fma.rn.f32x2 %0, %1, %2, %0;" : "+l"(d) : "l"(a), "l"(b));
}
__device__ __forceinline__ ull pack2(float lo, float hi) {
    ull r; asm("mov.b64 %0, {%1, %2};" : "=l"(r) : "f"(lo), "f"(hi)); return r;
}
__device__ __forceinline__ float hsum2(ull v) {
    float lo, hi;
    asm("mov.b64 {%0, %1}, %2;" : "=f"(lo), "=f"(hi) : "l"(v));
    return lo + hi;
}

// ---------------------------------------------------------------------------
// Kernel 1: transpose (B,3,N)+(B,64,N) channel-major -> (B,N,68) row-major
// ---------------------------------------------------------------------------
__global__ void __launch_bounds__(256) transpose_kernel(
    const float* __restrict__ xyz, const float* __restrict__ pts)
{
    __shared__ float sm[67 * 65];
    int b  = blockIdx.x >> 6;
    int n0 = (blockIdx.x & 63) << 6;
    int t  = threadIdx.x;
    for (int idx = t; idx < 67 * 64; idx += 256) {
        int c = idx >> 6, i = idx & 63;
        float v = (c < 3) ? xyz[(b * 3 + c) * N + n0 + i]
                          : pts[(b * 64 + (c - 3)) * N + n0 + i];
        sm[c * 65 + i] = v;
    }
    __syncthreads();
    for (int idx = t; idx < 64 * 17; idx += 256) {
        int row = idx / 17, c4 = idx % 17;
        int cb = c4 << 2;
        float4 v;
        v.x = sm[(cb + 0) * 65 + row];
        v.y = sm[(cb + 1) * 65 + row];
        v.z = sm[(cb + 2) * 65 + row];
        v.w = (cb + 3 < 67) ? sm[(cb + 3) * 65 + row] : 0.f;
        *(float4*)&g_xpt[((size_t)(b * N + n0 + row)) * 68 + cb] = v;
    }
}

// ---------------------------------------------------------------------------
// Shared-memory GEMM (f32x2 packed over K, compile-time K4, unroll 4):
// out[r][d] = relu(sum_k in[r][k]*W[d][k] + bias[d])
// in: 132 rows, stride 68.  W: rows are output channels, stride 68.
// Thread tiling: 4 rows x 8 cols per thread (cols strided by 8).
// ---------------------------------------------------------------------------
template<int K4>
__device__ __forceinline__ void gemm_relu2(
    const float* __restrict__ sIn, const float* __restrict__ sW,
    const float* __restrict__ sBias, float* __restrict__ sOut,
    int outStride, int dOff, int t)
{
    int d_blk = t & 7;
    int rb0   = t >> 3;
    for (int rb = rb0; rb < 33; rb += 32) {
        int r0 = rb << 2;
        ull acc[4][8];
#pragma unroll
        for (int i = 0; i < 4; i++)
#pragma unroll
            for (int j = 0; j < 8; j++) acc[i][j] = 0ull;
#pragma unroll 4
        for (int k4 = 0; k4 < K4; k4++) {
            ulonglong2 xv[4];
#pragma unroll
            for (int i = 0; i < 4; i++)
                xv[i] = *(const ulonglong2*)&sIn[(r0 + i) * 68 + (k4 << 2)];
#pragma unroll
            for (int j = 0; j < 8; j++) {
                ulonglong2 wv = *(const ulonglong2*)&sW[(dOff + d_blk + (j << 3)) * 68 + (k4 << 2)];
#pragma unroll
                for (int i = 0; i < 4; i++) {
                    ffma2(acc[i][j], xv[i].x, wv.x);
                    ffma2(acc[i][j], xv[i].y, wv.y);
                }
            }
        }
#pragma unroll
        for (int j = 0; j < 8; j++) {
            int d = dOff + d_blk + (j << 3);
            float bb = sBias[d];
#pragma unroll
            for (int i = 0; i < 4; i++) {
                float v = hsum2(acc[i][j]) + bb;
                sOut[(r0 + i) * outStride + d] = v > 0.f ? v : 0.f;
            }
        }
    }
}

// ---------------------------------------------------------------------------
// Main fused kernel: persistent CTAs, each tile = 4 groups (132 rows)
// smem layout (floats):
//  W1s 0(4352) W2s 4352(4352) W3s 8704(8704) c1 17408(64) c2 17472(64)
//  c3 17536(128) X 17664(8976) H1 26640(8976) H3 35616(17424)
//  relx 53040(384) nX 53424(16) rowGi 53440(132) -> 53572 floats
// 'a' (131x128 = 16768 fl) overlays X+H1 during the attention phase.
// ---------------------------------------------------------------------------
__global__ void __launch_bounds__(256, 1) main_kernel(
    const int* __restrict__ fpsIdx, const int* __restrict__ grpIdx,
    const float* __restrict__ w1, const float* __restrict__ b1,
    const float* __restrict__ g1, const float* __restrict__ bt1,
    const float* __restrict__ m1, const float* __restrict__ v1,
    const float* __restrict__ w2, const float* __restrict__ b2,
    const float* __restrict__ g2, const float* __restrict__ bt2,
    const float* __restrict__ m2, const float* __restrict__ v2,
    const float* __restrict__ w3, const float* __restrict__ b3,
    const float* __restrict__ g3, const float* __restrict__ bt3,
    const float* __restrict__ m3, const float* __restrict__ v3,
    const float* __restrict__ aG,
    float* __restrict__ out)
{
    extern __shared__ float sm[];
    float* W1s  = sm;
    float* W2s  = sm + 4352;
    float* W3s  = sm + 8704;
    float* c1s  = sm + 17408;
    float* c2s  = sm + 17472;
    float* c3s  = sm + 17536;
    float* X    = sm + 17664;   // also aSm during attention
    float* H1   = sm + 26640;
    float* H3   = sm + 35616;
    float* relx = sm + 53040;
    float* nX   = sm + 53424;
    int*  rowGi = (int*)(sm + 53440);
    float* aSm  = X;

    int t = threadIdx.x;

    // fold BN into weights (once per CTA)
    for (int idx = t; idx < 64 * 68; idx += 256) {
        int d = idx / 68, k = idx % 68;
        float s1 = g1[d] * rsqrtf(v1[d] + EPSBN);
        float s2 = g2[d] * rsqrtf(v2[d] + EPSBN);
        W1s[idx] = (k < 67) ? w1[d * 67 + k] * s1 : 0.f;
        W2s[idx] = (k < 64) ? w2[d * 64 + k] * s2 : 0.f;
    }
    for (int idx = t; idx < 128 * 68; idx += 256) {
        int d = idx / 68, k = idx % 68;
        float s3 = g3[d] * rsqrtf(v3[d] + EPSBN);
        W3s[idx] = (k < 64) ? w3[d * 64 + k] * s3 : 0.f;
    }
    if (t < 64) {
        float s1 = g1[t] * rsqrtf(v1[t] + EPSBN);
        float s2 = g2[t] * rsqrtf(v2[t] + EPSBN);
        c1s[t] = (b1[t] - m1[t]) * s1 + bt1[t];
        c2s[t] = (b2[t] - m2[t]) * s2 + bt2[t];
    }
    if (t < 128) {
        float s3 = g3[t] * rsqrtf(v3[t] + EPSBN);
        c3s[t] = (b3[t] - m3[t]) * s3 + bt3[t];
    }

    for (int tile = blockIdx.x; tile < NTILES; tile += gridDim.x) {
        __syncthreads();                       // protect smem from prev tile
        int b  = tile >> 8;
        int p0 = (tile & 255) << 2;

        if (t < 132) {
            int gi;
            if (t < 128) gi = grpIdx[((b * P + p0 + (t >> 5)) << 5) + (t & 31)];
            else         gi = fpsIdx[b * P + p0 + (t - 128)];
            rowGi[t] = gi;
        }
        __syncthreads();
        if (t < 12) {
            int p = t / 3, c = t % 3;
            float v = g_xpt[((size_t)(b * N + rowGi[128 + p])) * 68 + c];
            nX[p * 4 + c] = v;
            out[(b * 3 + c) * P + p0 + p] = v;   // new_xyz output (B,3,P)
        }
        __syncthreads();

        // gather 132 feature rows (67 valid floats each)
        for (int idx = t; idx < 132 * 17; idx += 256) {
            int row = idx / 17, c4 = idx % 17;
            float4 v = *(const float4*)&g_xpt[((size_t)(b * N + rowGi[row])) * 68 + (c4 << 2)];
            if (c4 == 0 && row < 128) {          // relative xyz for neighbor rows
                int p = row >> 5;
                v.x -= nX[p * 4 + 0];
                v.y -= nX[p * 4 + 1];
                v.z -= nX[p * 4 + 2];
                relx[row * 3 + 0] = v.x;
                relx[row * 3 + 1] = v.y;
                relx[row * 3 + 2] = v.z;
            }
            *(float4*)&X[row * 68 + (c4 << 2)] = v;
        }
        __syncthreads();

        gemm_relu2<17>(X,  W1s, c1s, H1, 68,  0,  t);   // 67 -> 64
        __syncthreads();
        gemm_relu2<16>(H1, W2s, c2s, X,  68,  0,  t);   // 64 -> 64 (H2 in X)
        __syncthreads();
        gemm_relu2<16>(X,  W3s, c3s, H3, 132, 0,  t);   // 64 -> 128
        gemm_relu2<16>(X,  W3s, c3s, H3, 132, 64, t);
        __syncthreads();

        // load attention matrix a into freed X+H1 region
        for (int idx = t; idx < (131 * 128) / 4; idx += 256)
            *(float4*)&aSm[idx << 2] = *(const float4*)&aG[idx << 2];
        __syncthreads();

        // attention: thread owns one (p,d) column; acc[0..31] = neighbor
        // H3 . a3  (f32x2 packed over k), acc[32] = fps row (== Fp term)
        int w = t >> 5, lane = t & 31;
        for (int pass = 0; pass < 2; pass++) {
            int pl = (pass << 1) + (w >> 2);         // local group 0..3
            int d  = ((w & 3) << 5) + lane;          // channel 0..127
            const float* hbase = &H3[(pl << 5) * 132];
            const float* hfps  = &H3[(128 + pl) * 132];
            ull acc[33];
#pragma unroll
            for (int r = 0; r < 33; r++) acc[r] = 0ull;
#pragma unroll 4
        for (int k4 = 0; k4 < 32; k4++) {
                int kb = 3 + (k4 << 2);
                float a0  = aSm[(kb + 0) * 128 + d];
                float a1  = aSm[(kb + 1) * 128 + d];
                float a2  = aSm[(kb + 2) * 128 + d];
                float a3v = aSm[(kb + 3) * 128 + d];
                ull ap0 = pack2(a0, a1);
                ull ap1 = pack2(a2, a3v);
#pragma unroll
                for (int r = 0; r < 32; r++) {
                    ulonglong2 h = *(const ulonglong2*)&hbase[r * 132 + (k4 << 2)];
                    ffma2(acc[r], h.x, ap0);
                    ffma2(acc[r], h.y, ap1);
                }
                ulonglong2 hf = *(const ulonglong2*)&hfps[k4 << 2];
                ffma2(acc[32], hf.x, ap0);
                ffma2(acc[32], hf.y, ap1);
            }
            float Fpd = hsum2(acc[32]);
            float av0 = aSm[d], av1 = aSm[128 + d], av2 = aSm[256 + d];
            float nx0 = nX[pl * 4 + 0], nx1 = nX[pl * 4 + 1], nx2 = nX[pl * 4 + 2];
            float ev_arr[32];
            float mx = -1e30f;
#pragma unroll
            for (int r = 0; r < 32; r++) {
                int row = (pl << 5) + r;
                float ev = Fpd - hsum2(acc[r])
                    + (nx0 - relx[row * 3 + 0]) * av0
                    + (nx1 - relx[row * 3 + 1]) * av1
                    + (nx2 - relx[row * 3 + 2]) * av2;
                ev = ev > 0.f ? ev : ALPHA * ev;      // leaky relu
                ev_arr[r] = ev;
                mx = fmaxf(mx, ev);
            }
            float ssum = 0.f;
#pragma unroll
            for (int r = 0; r < 32; r++) {
                float ee = __expf(ev_arr[r] - mx);
                ev_arr[r] = ee;
                ssum += ee;
            }
            float pooled = 0.f;
#pragma unroll
            for (int r = 0; r < 32; r++)
                pooled += ev_arr[r] * hbase[r * 132 + d];
            out[OUT2_OFF + (b * 128 + d) * P + p0 + pl] = pooled / ssum;
        }
    }
}

// ---------------------------------------------------------------------------
extern "C" void kernel_launch(void* const* d_in, const int* in_sizes, int n_in,
                              void* d_out, int out_size) {
    const float* xyz    = (const float*)d_in[0];
    const float* pts    = (const float*)d_in[1];
    const int*   fpsIdx = (const int*)d_in[2];
    const int*   grpIdx = (const int*)d_in[3];
    const float* w1 = (const float*)d_in[4];
    const float* b1 = (const float*)d_in[5];
    const float* g1 = (const float*)d_in[6];
    const float* bt1 = (const float*)d_in[7];
    const float* m1 = (const float*)d_in[8];
    const float* v1 = (const float*)d_in[9];
    const float* w2 = (const float*)d_in[10];
    const float* b2 = (const float*)d_in[11];
    const float* g2 = (const float*)d_in[12];
    const float* bt2 = (const float*)d_in[13];
    const float* m2 = (const float*)d_in[14];
    const float* v2 = (const float*)d_in[15];
    const float* w3 = (const float*)d_in[16];
    const float* b3 = (const float*)d_in[17];
    const float* g3 = (const float*)d_in[18];
    const float* bt3 = (const float*)d_in[19];
    const float* m3 = (const float*)d_in[20];
    const float* v3 = (const float*)d_in[21];
    const float* aG = (const float*)d_in[22];
    float* out = (float*)d_out;

    transpose_kernel<<<1024, 256>>>(xyz, pts);

    const int smBytes = 53572 * 4;   // 214288 B
    cudaFuncSetAttribute(main_kernel,
                         cudaFuncAttributeMaxDynamicSharedMemorySize, smBytes);
    int smCount = 148;
    cudaDeviceGetAttribute(&smCount, cudaDevAttrMultiProcessorCount, 0);

    main_kernel<<<smCount, 256, smBytes>>>(
        fpsIdx, grpIdx,
        w1, b1, g1, bt1, m1, v1,
        w2, b2, g2, bt2, m2, v2,
        w3, b3, g3, bt3, m3, v3,
        aG, out);
}